// round 5
// baseline (speedup 1.0000x reference)
#include <cuda_runtime.h>
#include <math.h>

#define N_NODES 100000
#define E_MAX   1600000
#define DIN 64
#define DH 128
#define DOUT 64

// Scratch (device globals: allocation-free rule).
__device__ __align__(16) int   g_cnt[N_NODES];                 // in-degree
__device__ __align__(16) int   g_start[N_NODES];               // CSR row offsets
__device__ __align__(16) int   g_cur[N_NODES];                 // fill cursors
__device__ __align__(16) int   g_csr[E_MAX];                   // CSR col (src) list
__device__ __align__(16) float g_agg1[(size_t)N_NODES * DIN];  // mean of x over in-edges
__device__ __align__(16) float g_h[(size_t)N_NODES * DH];      // layer1 output
__device__ __align__(16) float g_t[(size_t)N_NODES * DOUT];    // h @ W2l^T
__device__ __align__(16) float g_h2[(size_t)N_NODES * DOUT];   // h @ W2r^T + b2 (+= agg mean)

// ---------------------------------------------------------------- CSR build
__global__ void zero_cnt_kernel() {
    int i = blockIdx.x * blockDim.x + threadIdx.x;
    if (i < N_NODES) g_cnt[i] = 0;
}

// edge_index is int32 (JAX x64 disabled: astype(int64) -> int32). Layout [2, E].
__global__ void hist_kernel(const int* __restrict__ ei, int E) {
    int e = blockIdx.x * blockDim.x + threadIdx.x;
    if (e >= E) return;
    int dst = ei[E + e];
    atomicAdd(&g_cnt[dst], 1);
}

// Single-block scan of 100k counts.
__global__ void scan_kernel() {
    __shared__ int partial[1024];
    int t = threadIdx.x;
    const int CH = (N_NODES + 1023) / 1024;  // 98
    int beg = t * CH;
    int end = beg + CH; if (end > N_NODES) end = N_NODES;
    int s = 0;
    for (int i = beg; i < end; i++) s += g_cnt[i];
    partial[t] = s;
    __syncthreads();
    for (int off = 1; off < 1024; off <<= 1) {
        int v = partial[t];
        int add = (t >= off) ? partial[t - off] : 0;
        __syncthreads();
        partial[t] = v + add;
        __syncthreads();
    }
    int run = (t == 0) ? 0 : partial[t - 1];
    for (int i = beg; i < end; i++) {
        g_start[i] = run;
        g_cur[i] = run;
        run += g_cnt[i];
    }
}

__global__ void fill_kernel(const int* __restrict__ ei, int E) {
    int e = blockIdx.x * blockDim.x + threadIdx.x;
    if (e >= E) return;
    int src = ei[e];
    int dst = ei[E + e];
    int slot = atomicAdd(&g_cur[dst], 1);
    g_csr[slot] = src;
}

// ------------------------------------------------- aggregation 1 (gather-mean of x)
__global__ void agg1_kernel(const float* __restrict__ x) {
    int gw = (blockIdx.x * blockDim.x + threadIdx.x) >> 5;
    int lane = threadIdx.x & 31;
    int nwarps = (gridDim.x * blockDim.x) >> 5;
    for (int node = gw; node < N_NODES; node += nwarps) {
        int beg = g_start[node];
        int d = g_cnt[node];
        float a0 = 0.f, a1 = 0.f;
        int e = 0;
        for (; e + 4 <= d; e += 4) {
            int s0 = g_csr[beg + e + 0];
            int s1 = g_csr[beg + e + 1];
            int s2 = g_csr[beg + e + 2];
            int s3 = g_csr[beg + e + 3];
            a0 += x[(size_t)s0 * 64 + lane];  a1 += x[(size_t)s0 * 64 + lane + 32];
            a0 += x[(size_t)s1 * 64 + lane];  a1 += x[(size_t)s1 * 64 + lane + 32];
            a0 += x[(size_t)s2 * 64 + lane];  a1 += x[(size_t)s2 * 64 + lane + 32];
            a0 += x[(size_t)s3 * 64 + lane];  a1 += x[(size_t)s3 * 64 + lane + 32];
        }
        for (; e < d; e++) {
            int s0 = g_csr[beg + e];
            a0 += x[(size_t)s0 * 64 + lane];  a1 += x[(size_t)s0 * 64 + lane + 32];
        }
        float invd = 1.0f / fmaxf((float)d, 1.0f);
        g_agg1[(size_t)node * 64 + lane]      = a0 * invd;
        g_agg1[(size_t)node * 64 + lane + 32] = a1 * invd;
    }
}

// ------------------------------------------------- aggregation 2 (gather-mean of t, fused += h2)
__global__ void agg2_kernel() {
    int gw = (blockIdx.x * blockDim.x + threadIdx.x) >> 5;
    int lane = threadIdx.x & 31;
    int nwarps = (gridDim.x * blockDim.x) >> 5;
    for (int node = gw; node < N_NODES; node += nwarps) {
        int beg = g_start[node];
        int d = g_cnt[node];
        float a0 = 0.f, a1 = 0.f;
        int e = 0;
        for (; e + 4 <= d; e += 4) {
            int s0 = g_csr[beg + e + 0];
            int s1 = g_csr[beg + e + 1];
            int s2 = g_csr[beg + e + 2];
            int s3 = g_csr[beg + e + 3];
            a0 += g_t[(size_t)s0 * 64 + lane];  a1 += g_t[(size_t)s0 * 64 + lane + 32];
            a0 += g_t[(size_t)s1 * 64 + lane];  a1 += g_t[(size_t)s1 * 64 + lane + 32];
            a0 += g_t[(size_t)s2 * 64 + lane];  a1 += g_t[(size_t)s2 * 64 + lane + 32];
            a0 += g_t[(size_t)s3 * 64 + lane];  a1 += g_t[(size_t)s3 * 64 + lane + 32];
        }
        for (; e < d; e++) {
            int s0 = g_csr[beg + e];
            a0 += g_t[(size_t)s0 * 64 + lane];  a1 += g_t[(size_t)s0 * 64 + lane + 32];
        }
        float invd = 1.0f / fmaxf((float)d, 1.0f);
        g_h2[(size_t)node * 64 + lane]      += a0 * invd;
        g_h2[(size_t)node * 64 + lane + 32] += a1 * invd;
    }
}

// ------------------------------------------------- layer 1
// h[:, jb:jb+64] = relu(agg1 @ W1l^T + b1 + x @ W1r^T), gridDim.y selects j-half.
__global__ void layer1_kernel(const float* __restrict__ x,
                              const float* __restrict__ W1l,
                              const float* __restrict__ W1r,
                              const float* __restrict__ b1) {
    __shared__ float Wl[64 * 64];     // [k][jl]
    __shared__ float Wr[64 * 64];     // [k][jl]
    __shared__ float bsh[64];
    __shared__ float stage[8 * 256];  // per warp: xa0[64] xa1[64] xr0[64] xr1[64]

    int tid = threadIdx.x;
    int jb = blockIdx.y * 64;
    for (int idx = tid; idx < 64 * 64; idx += blockDim.x) {
        int jl = idx & 63, k = idx >> 6;
        Wl[k * 64 + jl] = W1l[(size_t)(jb + jl) * 64 + k];
        Wr[k * 64 + jl] = W1r[(size_t)(jb + jl) * 64 + k];
    }
    if (tid < 64) bsh[tid] = b1[jb + tid];
    __syncthreads();

    int warp = tid >> 5, lane = tid & 31;
    float* sA0 = stage + warp * 256;
    float* sA1 = sA0 + 64;
    float* sR0 = sA1 + 64;
    float* sR1 = sR0 + 64;
    int wg = blockIdx.x * 8 + warp;
    int wstride = gridDim.x * 8;
    const int NPAIR = N_NODES / 2;

    for (int p = wg; p < NPAIR; p += wstride) {
        int n0 = p * 2, n1 = n0 + 1;
        sA0[lane]      = g_agg1[(size_t)n0 * 64 + lane];
        sA0[lane + 32] = g_agg1[(size_t)n0 * 64 + lane + 32];
        sA1[lane]      = g_agg1[(size_t)n1 * 64 + lane];
        sA1[lane + 32] = g_agg1[(size_t)n1 * 64 + lane + 32];
        sR0[lane]      = x[(size_t)n0 * 64 + lane];
        sR0[lane + 32] = x[(size_t)n0 * 64 + lane + 32];
        sR1[lane]      = x[(size_t)n1 * 64 + lane];
        sR1[lane + 32] = x[(size_t)n1 * 64 + lane + 32];
        __syncwarp();

        float b0 = bsh[lane], b1v = bsh[lane + 32];
        float a00 = b0, a01 = b1v;   // node0, j = lane / lane+32
        float a10 = b0, a11 = b1v;   // node1
#pragma unroll 8
        for (int k = 0; k < 64; k++) {
            float xa0 = sA0[k], xa1 = sA1[k];
            float xr0 = sR0[k], xr1 = sR1[k];
            float wl0 = Wl[k * 64 + lane], wl1 = Wl[k * 64 + lane + 32];
            float wr0 = Wr[k * 64 + lane], wr1 = Wr[k * 64 + lane + 32];
            a00 += xa0 * wl0 + xr0 * wr0;
            a01 += xa0 * wl1 + xr0 * wr1;
            a10 += xa1 * wl0 + xr1 * wr0;
            a11 += xa1 * wl1 + xr1 * wr1;
        }
        g_h[(size_t)n0 * 128 + jb + lane]      = fmaxf(a00, 0.f);
        g_h[(size_t)n0 * 128 + jb + lane + 32] = fmaxf(a01, 0.f);
        g_h[(size_t)n1 * 128 + jb + lane]      = fmaxf(a10, 0.f);
        g_h[(size_t)n1 * 128 + jb + lane + 32] = fmaxf(a11, 0.f);
        __syncwarp();
    }
}

// ------------------------------------------------- layer 2 pre
// t[:, jb:jb+32] = h @ W2l^T ; h2[:, jb:jb+32] = h @ W2r^T + b2. gridDim.y = 2 halves.
__global__ void layer2pre_kernel(const float* __restrict__ W2l,
                                 const float* __restrict__ W2r,
                                 const float* __restrict__ b2) {
    __shared__ float Wl[128 * 32];    // [k][jl]
    __shared__ float Wr[128 * 32];    // [k][jl]
    __shared__ float bsh[32];
    __shared__ float stage[8 * 256];  // per warp: h0[128] h1[128]

    int tid = threadIdx.x;
    int jb = blockIdx.y * 32;
    for (int idx = tid; idx < 128 * 32; idx += blockDim.x) {
        int jl = idx & 31, k = idx >> 5;
        Wl[k * 32 + jl] = W2l[(size_t)(jb + jl) * 128 + k];
        Wr[k * 32 + jl] = W2r[(size_t)(jb + jl) * 128 + k];
    }
    if (tid < 32) bsh[tid] = b2[jb + tid];
    __syncthreads();

    int warp = tid >> 5, lane = tid & 31;
    float* sh0 = stage + warp * 256;
    float* sh1 = sh0 + 128;
    int wg = blockIdx.x * 8 + warp;
    int wstride = gridDim.x * 8;
    const int NPAIR = N_NODES / 2;

    for (int p = wg; p < NPAIR; p += wstride) {
        int n0 = p * 2, n1 = n0 + 1;
        sh0[lane]      = g_h[(size_t)n0 * 128 + lane];
        sh0[lane + 32] = g_h[(size_t)n0 * 128 + lane + 32];
        sh0[lane + 64] = g_h[(size_t)n0 * 128 + lane + 64];
        sh0[lane + 96] = g_h[(size_t)n0 * 128 + lane + 96];
        sh1[lane]      = g_h[(size_t)n1 * 128 + lane];
        sh1[lane + 32] = g_h[(size_t)n1 * 128 + lane + 32];
        sh1[lane + 64] = g_h[(size_t)n1 * 128 + lane + 64];
        sh1[lane + 96] = g_h[(size_t)n1 * 128 + lane + 96];
        __syncwarp();

        float bb = bsh[lane];
        float t0 = 0.f, t1 = 0.f;
        float h0 = bb, h1v = bb;
#pragma unroll 8
        for (int k = 0; k < 128; k++) {
            float v0 = sh0[k], v1 = sh1[k];
            float wl = Wl[k * 32 + lane];
            float wr = Wr[k * 32 + lane];
            t0  += v0 * wl;
            h0  += v0 * wr;
            t1  += v1 * wl;
            h1v += v1 * wr;
        }
        g_t[(size_t)n0 * 64 + jb + lane]  = t0;
        g_h2[(size_t)n0 * 64 + jb + lane] = h0;
        g_t[(size_t)n1 * 64 + jb + lane]  = t1;
        g_h2[(size_t)n1 * 64 + jb + lane] = h1v;
        __syncwarp();
    }
}

// ------------------------------------------------- link prediction: warp per pair
// pairs is int32, layout [P, 2].
__global__ void predict_kernel(const int* __restrict__ pairs,
                               const float* __restrict__ Wlp,
                               const float* __restrict__ blp,
                               float* __restrict__ out, int P) {
    int g = blockIdx.x * blockDim.x + threadIdx.x;
    int p = g >> 5;
    int lane = g & 31;
    if (p >= P) return;
    int s = pairs[p * 2];
    int d = pairs[p * 2 + 1];
    float w0 = Wlp[lane], w1 = Wlp[lane + 32], w2 = Wlp[lane + 64], w3 = Wlp[lane + 96];
    float v = g_h2[(size_t)s * 64 + lane] * w0
            + g_h2[(size_t)s * 64 + lane + 32] * w1
            + g_h2[(size_t)d * 64 + lane] * w2
            + g_h2[(size_t)d * 64 + lane + 32] * w3;
#pragma unroll
    for (int o = 16; o; o >>= 1) v += __shfl_xor_sync(0xFFFFFFFFu, v, o);
    if (lane == 0) out[p] = 1.0f / (1.0f + expf(-(v + blp[0])));
}

// ----------------------------------------------------------------------------
extern "C" void kernel_launch(void* const* d_in, const int* in_sizes, int n_in,
                              void* d_out, int out_size) {
    const float* x   = (const float*)d_in[0];
    const int* ei    = (const int*)d_in[1];    // int32! (JAX x64 disabled)
    const int* prs   = (const int*)d_in[2];    // int32!
    const float* W1l = (const float*)d_in[3];
    const float* W1r = (const float*)d_in[4];
    const float* b1  = (const float*)d_in[5];
    const float* W2l = (const float*)d_in[6];
    const float* W2r = (const float*)d_in[7];
    const float* b2  = (const float*)d_in[8];
    const float* Wlp = (const float*)d_in[9];
    const float* blp = (const float*)d_in[10];
    float* out       = (float*)d_out;

    int E = in_sizes[1] / 2;
    int P = in_sizes[2] / 2;
    int eblocks = (E + 255) / 256;

    // CSR build
    zero_cnt_kernel<<<(N_NODES + 255) / 256, 256>>>();
    hist_kernel<<<eblocks, 256>>>(ei, E);
    scan_kernel<<<1, 1024>>>();
    fill_kernel<<<eblocks, 256>>>(ei, E);

    // Layer 1
    agg1_kernel<<<1024, 256>>>(x);
    dim3 l1grid(200, 2);
    layer1_kernel<<<l1grid, 256>>>(x, W1l, W1r, b1);

    // Layer 2 (linearity: aggregate t = h@W2l^T instead of h)
    dim3 l2grid(200, 2);
    layer2pre_kernel<<<l2grid, 256>>>(W2l, W2r, b2);
    agg2_kernel<<<1024, 256>>>();

    // Link prediction
    int pblocks = (P * 32 + 255) / 256;
    predict_kernel<<<pblocks, 256>>>(prs, Wlp, blp, out, P);
}

// round 7
// speedup vs baseline: 1.4250x; 1.4250x over previous
#include <cuda_runtime.h>
#include <math.h>

#define N_NODES 100000
#define E_MAX   1600000
#define DIN 64
#define DH 128
#define DOUT 64

// Scratch (device globals: allocation-free rule).
__device__ __align__(16) int   g_cnt[N_NODES];
__device__ __align__(16) int   g_start[N_NODES];
__device__ __align__(16) int   g_cur[N_NODES];
__device__ __align__(16) int   g_csr[E_MAX];
__device__ __align__(16) float g_agg1[(size_t)N_NODES * DIN];
__device__ __align__(16) float g_h[(size_t)N_NODES * DH];
__device__ __align__(16) float g_t[(size_t)N_NODES * DOUT];
__device__ __align__(16) float g_h2[(size_t)N_NODES * DOUT];

// ---------------------------------------------------------------- CSR build
__global__ void zero_cnt_kernel() {
    int i = blockIdx.x * blockDim.x + threadIdx.x;
    if (i < N_NODES) g_cnt[i] = 0;
}

// edge_index is int32, layout [2, E]. 4 edges per thread via int4.
__global__ void hist_kernel(const int* __restrict__ ei, int E) {
    int i = blockIdx.x * blockDim.x + threadIdx.x;
    int e4 = i * 4;
    if (e4 + 3 < E) {
        int4 d4 = *(const int4*)&ei[E + e4];
        atomicAdd(&g_cnt[d4.x], 1);
        atomicAdd(&g_cnt[d4.y], 1);
        atomicAdd(&g_cnt[d4.z], 1);
        atomicAdd(&g_cnt[d4.w], 1);
    } else {
        for (int e = e4; e < E; e++) atomicAdd(&g_cnt[ei[E + e]], 1);
    }
}

// Single-block scan of 100k counts; 1000 active threads x 100 elems, int4 I/O.
__global__ void scan_kernel() {
    __shared__ int partial[1024];
    int t = threadIdx.x;
    int s = 0;
    if (t < 1000) {
        const int4* c4 = (const int4*)&g_cnt[t * 100];
#pragma unroll
        for (int i = 0; i < 25; i++) {
            int4 v = c4[i];
            s += v.x + v.y + v.z + v.w;
        }
    }
    partial[t] = s;
    __syncthreads();
    for (int off = 1; off < 1024; off <<= 1) {
        int v = partial[t];
        int add = (t >= off) ? partial[t - off] : 0;
        __syncthreads();
        partial[t] = v + add;
        __syncthreads();
    }
    if (t < 1000) {
        int run = (t == 0) ? 0 : partial[t - 1];
        const int4* c4 = (const int4*)&g_cnt[t * 100];
        int4* s4 = (int4*)&g_start[t * 100];
        int4* u4 = (int4*)&g_cur[t * 100];
#pragma unroll
        for (int i = 0; i < 25; i++) {
            int4 c = c4[i];
            int4 st;
            st.x = run; run += c.x;
            st.y = run; run += c.y;
            st.z = run; run += c.z;
            st.w = run; run += c.w;
            s4[i] = st;
            u4[i] = st;
        }
    }
}

__global__ void fill_kernel(const int* __restrict__ ei, int E) {
    int i = blockIdx.x * blockDim.x + threadIdx.x;
    int e4 = i * 4;
    if (e4 + 3 < E) {
        int4 s4 = *(const int4*)&ei[e4];
        int4 d4 = *(const int4*)&ei[E + e4];
        g_csr[atomicAdd(&g_cur[d4.x], 1)] = s4.x;
        g_csr[atomicAdd(&g_cur[d4.y], 1)] = s4.y;
        g_csr[atomicAdd(&g_cur[d4.z], 1)] = s4.z;
        g_csr[atomicAdd(&g_cur[d4.w], 1)] = s4.w;
    } else {
        for (int e = e4; e < E; e++)
            g_csr[atomicAdd(&g_cur[ei[E + e]], 1)] = ei[e];
    }
}

// ------------------------------------------------- aggregation 1: gather-mean of x rows
// Warp per node; lane owns one float2 of the 64-dim row (32 x 8B = 256B/row).
__global__ void agg1_kernel(const float* __restrict__ x) {
    int gw = (blockIdx.x * blockDim.x + threadIdx.x) >> 5;
    int lane = threadIdx.x & 31;
    int nwarps = (gridDim.x * blockDim.x) >> 5;
    const float2* x2 = (const float2*)x;
    for (int node = gw; node < N_NODES; node += nwarps) {
        int beg = g_start[node];
        int d = g_cnt[node];
        float2 a = make_float2(0.f, 0.f);
        int e = 0;
        for (; e + 4 <= d; e += 4) {
            int s0 = g_csr[beg + e + 0];
            int s1 = g_csr[beg + e + 1];
            int s2 = g_csr[beg + e + 2];
            int s3 = g_csr[beg + e + 3];
            float2 v0 = x2[(size_t)s0 * 32 + lane];
            float2 v1 = x2[(size_t)s1 * 32 + lane];
            float2 v2 = x2[(size_t)s2 * 32 + lane];
            float2 v3 = x2[(size_t)s3 * 32 + lane];
            a.x += v0.x + v1.x + v2.x + v3.x;
            a.y += v0.y + v1.y + v2.y + v3.y;
        }
        for (; e < d; e++) {
            int s0 = g_csr[beg + e];
            float2 v0 = x2[(size_t)s0 * 32 + lane];
            a.x += v0.x;
            a.y += v0.y;
        }
        float invd = 1.0f / fmaxf((float)d, 1.0f);
        ((float2*)g_agg1)[(size_t)node * 32 + lane] = make_float2(a.x * invd, a.y * invd);
    }
}

// ------------------------------------------------- aggregation 2: gather-mean of t, fused += h2
__global__ void agg2_kernel() {
    int gw = (blockIdx.x * blockDim.x + threadIdx.x) >> 5;
    int lane = threadIdx.x & 31;
    int nwarps = (gridDim.x * blockDim.x) >> 5;
    const float2* t2 = (const float2*)g_t;
    for (int node = gw; node < N_NODES; node += nwarps) {
        int beg = g_start[node];
        int d = g_cnt[node];
        float2 a = make_float2(0.f, 0.f);
        int e = 0;
        for (; e + 4 <= d; e += 4) {
            int s0 = g_csr[beg + e + 0];
            int s1 = g_csr[beg + e + 1];
            int s2 = g_csr[beg + e + 2];
            int s3 = g_csr[beg + e + 3];
            float2 v0 = t2[(size_t)s0 * 32 + lane];
            float2 v1 = t2[(size_t)s1 * 32 + lane];
            float2 v2 = t2[(size_t)s2 * 32 + lane];
            float2 v3 = t2[(size_t)s3 * 32 + lane];
            a.x += v0.x + v1.x + v2.x + v3.x;
            a.y += v0.y + v1.y + v2.y + v3.y;
        }
        for (; e < d; e++) {
            int s0 = g_csr[beg + e];
            float2 v0 = t2[(size_t)s0 * 32 + lane];
            a.x += v0.x;
            a.y += v0.y;
        }
        float invd = 1.0f / fmaxf((float)d, 1.0f);
        float2* o = &((float2*)g_h2)[(size_t)node * 32 + lane];
        float2 cur = *o;
        cur.x += a.x * invd;
        cur.y += a.y * invd;
        *o = cur;
    }
}

// ------------------------------------------------- layer 1 (combined GEMM, k=128)
// h[:, jb:jb+64] = relu([agg1|x] @ [W1l|W1r](jb:jb+64)^T + b1), gridDim.y picks j-half.
// 4 nodes per warp; float2 weight LDS; broadcast stage LDS.
__global__ void layer1_kernel(const float* __restrict__ x,
                              const float* __restrict__ W1l,
                              const float* __restrict__ W1r,
                              const float* __restrict__ b1) {
    __shared__ float Wc[128 * 64];      // [k][jl], 32KB
    __shared__ float stage[8][4 * 128]; // per warp: 4 nodes x (agg[64]|x[64]), 16KB

    int tid = threadIdx.x;
    int jb = blockIdx.y * 64;
    for (int idx = tid; idx < 128 * 64; idx += blockDim.x) {
        int jl = idx & 63, k = idx >> 6;
        Wc[k * 64 + jl] = (k < 64) ? W1l[(size_t)(jb + jl) * 64 + k]
                                   : W1r[(size_t)(jb + jl) * 64 + (k - 64)];
    }
    __syncthreads();

    int warp = tid >> 5, lane = tid & 31;
    float* st = stage[warp];
    float2 bv = *(const float2*)&b1[jb + lane * 2];

    int wg = blockIdx.x * 8 + warp;
    int wstride = gridDim.x * 8;
    const int NQUAD = N_NODES / 4;

    for (int q = wg; q < NQUAD; q += wstride) {
        int n0 = q * 4;
#pragma unroll
        for (int n = 0; n < 4; n++) {
            size_t node = (size_t)(n0 + n);
            st[n * 128 + lane]      = g_agg1[node * 64 + lane];
            st[n * 128 + 32 + lane] = g_agg1[node * 64 + 32 + lane];
            st[n * 128 + 64 + lane] = x[node * 64 + lane];
            st[n * 128 + 96 + lane] = x[node * 64 + 32 + lane];
        }
        __syncwarp();

        float a0x = bv.x, a0y = bv.y, a1x = bv.x, a1y = bv.y;
        float a2x = bv.x, a2y = bv.y, a3x = bv.x, a3y = bv.y;
#pragma unroll 4
        for (int k = 0; k < 128; k++) {
            float2 w = *(const float2*)&Wc[k * 64 + lane * 2];
            float s0 = st[k];
            float s1 = st[128 + k];
            float s2 = st[256 + k];
            float s3 = st[384 + k];
            a0x += s0 * w.x; a0y += s0 * w.y;
            a1x += s1 * w.x; a1y += s1 * w.y;
            a2x += s2 * w.x; a2y += s2 * w.y;
            a3x += s3 * w.x; a3y += s3 * w.y;
        }
        float2* hp = (float2*)&g_h[(size_t)n0 * 128 + jb + lane * 2];
        hp[0]       = make_float2(fmaxf(a0x, 0.f), fmaxf(a0y, 0.f));
        hp[64]      = make_float2(fmaxf(a1x, 0.f), fmaxf(a1y, 0.f));
        hp[128]     = make_float2(fmaxf(a2x, 0.f), fmaxf(a2y, 0.f));
        hp[192]     = make_float2(fmaxf(a3x, 0.f), fmaxf(a3y, 0.f));
        __syncwarp();
    }
}

// ------------------------------------------------- layer 2 (two GEMMs via gridDim.y)
// y=0: g_t = h @ W2l^T (no bias); y=1: g_h2 = h @ W2r^T + b2.
__global__ void layer2_kernel(const float* __restrict__ W2l,
                              const float* __restrict__ W2r,
                              const float* __restrict__ b2) {
    __shared__ float Wc[128 * 64];      // [k][jl], 32KB
    __shared__ float stage[8][4 * 128]; // 4 nodes x h[128], 16KB

    int tid = threadIdx.x;
    int ysel = blockIdx.y;
    const float* W = ysel ? W2r : W2l;
    float* outbuf = ysel ? g_h2 : g_t;
    for (int idx = tid; idx < 128 * 64; idx += blockDim.x) {
        int jl = idx & 63, k = idx >> 6;
        Wc[k * 64 + jl] = W[(size_t)jl * 128 + k];
    }
    __syncthreads();

    int warp = tid >> 5, lane = tid & 31;
    float* st = stage[warp];
    float2 bv = ysel ? *(const float2*)&b2[lane * 2] : make_float2(0.f, 0.f);

    int wg = blockIdx.x * 8 + warp;
    int wstride = gridDim.x * 8;
    const int NQUAD = N_NODES / 4;

    for (int q = wg; q < NQUAD; q += wstride) {
        int n0 = q * 4;
#pragma unroll
        for (int n = 0; n < 4; n++) {
            size_t node = (size_t)(n0 + n);
            st[n * 128 + lane]      = g_h[node * 128 + lane];
            st[n * 128 + 32 + lane] = g_h[node * 128 + 32 + lane];
            st[n * 128 + 64 + lane] = g_h[node * 128 + 64 + lane];
            st[n * 128 + 96 + lane] = g_h[node * 128 + 96 + lane];
        }
        __syncwarp();

        float a0x = bv.x, a0y = bv.y, a1x = bv.x, a1y = bv.y;
        float a2x = bv.x, a2y = bv.y, a3x = bv.x, a3y = bv.y;
#pragma unroll 4
        for (int k = 0; k < 128; k++) {
            float2 w = *(const float2*)&Wc[k * 64 + lane * 2];
            float s0 = st[k];
            float s1 = st[128 + k];
            float s2 = st[256 + k];
            float s3 = st[384 + k];
            a0x += s0 * w.x; a0y += s0 * w.y;
            a1x += s1 * w.x; a1y += s1 * w.y;
            a2x += s2 * w.x; a2y += s2 * w.y;
            a3x += s3 * w.x; a3y += s3 * w.y;
        }
        float2* op = (float2*)&outbuf[(size_t)n0 * 64 + lane * 2];
        op[0]  = make_float2(a0x, a0y);
        op[32] = make_float2(a1x, a1y);
        op[64] = make_float2(a2x, a2y);
        op[96] = make_float2(a3x, a3y);
        __syncwarp();
    }
}

// ------------------------------------------------- link prediction: warp per pair
__global__ void predict_kernel(const int* __restrict__ pairs,
                               const float* __restrict__ Wlp,
                               const float* __restrict__ blp,
                               float* __restrict__ out, int P) {
    int g = blockIdx.x * blockDim.x + threadIdx.x;
    int p = g >> 5;
    int lane = g & 31;
    if (p >= P) return;
    int2 sd = *(const int2*)&pairs[p * 2];
    float w0 = Wlp[lane], w1 = Wlp[lane + 32], w2 = Wlp[lane + 64], w3 = Wlp[lane + 96];
    float v = g_h2[(size_t)sd.x * 64 + lane] * w0
            + g_h2[(size_t)sd.x * 64 + lane + 32] * w1
            + g_h2[(size_t)sd.y * 64 + lane] * w2
            + g_h2[(size_t)sd.y * 64 + lane + 32] * w3;
#pragma unroll
    for (int o = 16; o; o >>= 1) v += __shfl_xor_sync(0xFFFFFFFFu, v, o);
    if (lane == 0) out[p] = 1.0f / (1.0f + expf(-(v + blp[0])));
}

// ----------------------------------------------------------------------------
extern "C" void kernel_launch(void* const* d_in, const int* in_sizes, int n_in,
                              void* d_out, int out_size) {
    const float* x   = (const float*)d_in[0];
    const int* ei    = (const int*)d_in[1];    // int32 (JAX x64 disabled)
    const int* prs   = (const int*)d_in[2];    // int32
    const float* W1l = (const float*)d_in[3];
    const float* W1r = (const float*)d_in[4];
    const float* b1  = (const float*)d_in[5];
    const float* W2l = (const float*)d_in[6];
    const float* W2r = (const float*)d_in[7];
    const float* b2  = (const float*)d_in[8];
    const float* Wlp = (const float*)d_in[9];
    const float* blp = (const float*)d_in[10];
    float* out       = (float*)d_out;

    int E = in_sizes[1] / 2;
    int P = in_sizes[2] / 2;
    int e4blocks = ((E + 3) / 4 + 255) / 256;

    // CSR build
    zero_cnt_kernel<<<(N_NODES + 255) / 256, 256>>>();
    hist_kernel<<<e4blocks, 256>>>(ei, E);
    scan_kernel<<<1, 1024>>>();
    fill_kernel<<<e4blocks, 256>>>(ei, E);

    // Layer 1
    agg1_kernel<<<1024, 256>>>(x);
    dim3 l1grid(256, 2);
    layer1_kernel<<<l1grid, 256>>>(x, W1l, W1r, b1);

    // Layer 2 (linearity: aggregate t = h@W2l^T instead of h)
    dim3 l2grid(256, 2);
    layer2_kernel<<<l2grid, 256>>>(W2l, W2r, b2);
    agg2_kernel<<<1024, 256>>>();

    // Link prediction
    int pblocks = (P * 32 + 255) / 256;
    predict_kernel<<<pblocks, 256>>>(prs, Wlp, blp, out, P);
}